// round 1
// baseline (speedup 1.0000x reference)
#include <cuda_runtime.h>
#include <cuda_bf16.h>

// Problem constants (match setup_inputs in the reference)
#define BS 2
#define NQ 8192
#define NV 6890
#define NF 13776
#define EPSF 1e-7f
#define R2F 0.01f        // f32(0.1*0.1 in double) — matches JAX constant folding
#define NEG_R (-0.1f)
#define THRESHF 0.001f

// Scratch (no allocations allowed — device globals)
__device__ float g_vnsum[BS * NV * 3];   // vertex-normal accumulators
__device__ float g_vncnt[BS * NV];       // incident-face counts (float, as in ref)
__device__ float g_perpt[BS * NQ];       // per-query squared loss terms

// ---------------------------------------------------------------------------
// Kernel 0: zero the scatter accumulators (must re-zero every graph replay)
// ---------------------------------------------------------------------------
__global__ void zero_kernel() {
    int i = blockIdx.x * blockDim.x + threadIdx.x;
    if (i < BS * NV * 3) g_vnsum[i] = 0.0f;
    if (i < BS * NV)     g_vncnt[i] = 0.0f;
}

// ---------------------------------------------------------------------------
// Kernel 1: face normals -> scatter-add to vertex accumulators
// h_faces: (b, 3, NF) int32 ; h_state: (b, 6, NV) f32 (rows 0..2 = x,y,z)
// ---------------------------------------------------------------------------
__global__ void face_scatter_kernel(const float* __restrict__ h_state,
                                    const int* __restrict__ h_faces) {
    int t = blockIdx.x * blockDim.x + threadIdx.x;
    if (t >= BS * NF) return;
    int b = t / NF;
    int f = t - b * NF;

    const int* F = h_faces + b * 3 * NF;
    int i0 = F[f];
    int i1 = F[NF + f];
    int i2 = F[2 * NF + f];

    const float* xs = h_state + b * 6 * NV;
    const float* ys = xs + NV;
    const float* zs = xs + 2 * NV;

    float x0 = xs[i0], y0 = ys[i0], z0 = zs[i0];
    float e1x = xs[i1] - x0, e1y = ys[i1] - y0, e1z = zs[i1] - z0;
    float e2x = xs[i2] - x0, e2y = ys[i2] - y0, e2z = zs[i2] - z0;

    float nx = e1y * e2z - e1z * e2y;
    float ny = e1z * e2x - e1x * e2z;
    float nz = e1x * e2y - e1y * e2x;
    float nrm = sqrtf(nx * nx + ny * ny + nz * nz) + EPSF;
    nx /= nrm; ny /= nrm; nz /= nrm;

    int base = b * NV;
    int vi0 = base + i0, vi1 = base + i1, vi2 = base + i2;
    atomicAdd(&g_vnsum[vi0 * 3 + 0], nx);
    atomicAdd(&g_vnsum[vi0 * 3 + 1], ny);
    atomicAdd(&g_vnsum[vi0 * 3 + 2], nz);
    atomicAdd(&g_vncnt[vi0], 1.0f);
    atomicAdd(&g_vnsum[vi1 * 3 + 0], nx);
    atomicAdd(&g_vnsum[vi1 * 3 + 1], ny);
    atomicAdd(&g_vnsum[vi1 * 3 + 2], nz);
    atomicAdd(&g_vncnt[vi1], 1.0f);
    atomicAdd(&g_vnsum[vi2 * 3 + 0], nx);
    atomicAdd(&g_vnsum[vi2 * 3 + 1], ny);
    atomicAdd(&g_vnsum[vi2 * 3 + 2], nz);
    atomicAdd(&g_vncnt[vi2], 1.0f);
}

// ---------------------------------------------------------------------------
// Kernel 2: ball query (first 4 in index order, early-exit) + per-query loss.
// One warp per query point; ballot over 32 consecutive vertices preserves
// index order; all lanes replicate the slot bookkeeping (same ballot value).
// ---------------------------------------------------------------------------
__global__ void __launch_bounds__(256)
query_loss_kernel(const float* __restrict__ pred,
                  const float* __restrict__ h_state) {
    int gwid = (blockIdx.x * blockDim.x + threadIdx.x) >> 5;
    int lane = threadIdx.x & 31;
    if (gwid >= BS * NQ) return;
    int b = gwid / NQ;
    int q = gwid - b * NQ;

    const float* P = pred + (size_t)(b * NQ + q) * 3;
    float px = P[0], py = P[1], pz = P[2];

    const float* xs = h_state + b * 6 * NV;
    const float* ys = xs + NV;
    const float* zs = xs + 2 * NV;

    int idx[4];
    int cnt = 0;

    for (int base = 0; base < NV; base += 32) {
        int v = base + lane;
        bool inr = (v < NV);
        int vc = inr ? v : (NV - 1);
        float dx = px - __ldg(xs + vc);
        float dy = py - __ldg(ys + vc);
        float dz = pz - __ldg(zs + vc);
        float d2 = dx * dx + dy * dy + dz * dz;
        unsigned m = __ballot_sync(0xffffffffu, inr && (d2 < R2F));
        while (m && cnt < 4) {
            int bit = __ffs(m) - 1;
            idx[cnt++] = base + bit;
            m &= (m - 1);
        }
        if (cnt == 4) break;
    }

    if (lane == 0) {
        int first = (cnt > 0) ? idx[0] : 0;   // argmax(within)=0 when no hits
        for (int j = cnt; j < 4; j++) idx[j] = first;

        float s = 0.0f, nm = 0.0f;
        #pragma unroll
        for (int j = 0; j < 4; j++) {
            int i = idx[j];
            float vx = xs[i], vy = ys[i], vz = zs[i];
            float c = g_vncnt[b * NV + i];
            float denom = c + EPSF;
            float gx = g_vnsum[(b * NV + i) * 3 + 0] / denom;
            float gy = g_vnsum[(b * NV + i) * 3 + 1] / denom;
            float gz = g_vnsum[(b * NV + i) * 3 + 2] / denom;
            float nr = sqrtf(gx * gx + gy * gy + gz * gz) + EPSF;
            gx /= nr; gy /= nr; gz /= nr;
            float dot = (px - vx) * gx + (py - vy) * gy + (pz - vz) * gz;
            float valid = (dot >= NEG_R) ? (dot - THRESHF) : 0.0f;
            if (valid < 0.0f) { s += valid; nm += 1.0f; }
        }
        float pp = s / (nm + EPSF);
        g_perpt[gwid] = pp * pp;
    }
}

// ---------------------------------------------------------------------------
// Kernel 3: deterministic reduction of per-query terms -> scalar loss
// ---------------------------------------------------------------------------
__global__ void finalize_kernel(float* __restrict__ out) {
    __shared__ float ssum[512];
    __shared__ float scnt[512];
    int t = threadIdx.x;
    float s = 0.0f, c = 0.0f;
    for (int i = t; i < BS * NQ; i += 512) {
        float v = g_perpt[i];
        s += v;
        c += (v > 0.0f) ? 1.0f : 0.0f;
    }
    ssum[t] = s;
    scnt[t] = c;
    __syncthreads();
    for (int o = 256; o > 0; o >>= 1) {
        if (t < o) { ssum[t] += ssum[t + o]; scnt[t] += scnt[t + o]; }
        __syncthreads();
    }
    if (t == 0) out[0] = ssum[0] / (scnt[0] + EPSF);   // LOSS_WEIGHT = 1
}

// ---------------------------------------------------------------------------
extern "C" void kernel_launch(void* const* d_in, const int* in_sizes, int n_in,
                              void* d_out, int out_size) {
    const float* pred    = (const float*)d_in[0];   // (2, 8192, 3)
    // d_in[1] = label (unused)
    const float* h_state = (const float*)d_in[2];   // (2, 6, 6890)
    const int*   h_faces = (const int*)d_in[3];     // (2, 3, 13776)
    float* out = (float*)d_out;

    int zero_n = BS * NV * 3;
    zero_kernel<<<(zero_n + 255) / 256, 256>>>();

    int faces_n = BS * NF;
    face_scatter_kernel<<<(faces_n + 255) / 256, 256>>>(h_state, h_faces);

    int total_warps = BS * NQ;                     // one warp per query
    int threads = 256;                             // 8 warps/block
    int blocks = (total_warps * 32 + threads - 1) / threads;
    query_loss_kernel<<<blocks, threads>>>(pred, h_state);

    finalize_kernel<<<1, 512>>>(out);
}

// round 2
// speedup vs baseline: 1.9019x; 1.9019x over previous
#include <cuda_runtime.h>
#include <cuda_bf16.h>

#define BS 2
#define NQ 8192
#define NV 6890
#define NF 13776
#define EPSF 1e-7f
#define R2F 0.01f        // f32(0.1*0.1) — matches JAX constant folding
#define NEG_R (-0.1f)
#define THRESHF 0.001f

#define GRIDC 10
#define NCELL (GRIDC * GRIDC)
#define CAP 256          // max verts per (x,y) cell; mean ~69, P(>256) ~ 0
#define IMAXI 0x7fffffff
#define QBLOCKS (BS * NQ / 8)   // 2048 query blocks (8 warps each)

// Scratch — device globals only (no allocations allowed)
__device__ float  g_vnsum[BS * NV * 3];
__device__ float  g_vncnt[BS * NV];
__device__ int    g_cellcnt[BS * NCELL];
__device__ float4 g_bins[BS * NCELL * CAP];
__device__ float  g_psum[QBLOCKS];
__device__ float  g_pcnt[QBLOCKS];

// ---------------------------------------------------------------------------
// K0: zero accumulators and cell counters (re-zeroed every graph replay)
// ---------------------------------------------------------------------------
__global__ void zero_kernel() {
    int i = blockIdx.x * blockDim.x + threadIdx.x;
    if (i < BS * NV * 3) g_vnsum[i] = 0.0f;
    if (i < BS * NV)     g_vncnt[i] = 0.0f;
    if (i < BS * NCELL)  g_cellcnt[i] = 0;
}

// ---------------------------------------------------------------------------
// K1: fused — face-normal scatter AND vertex binning (counting-free bins:
// fixed-capacity slots claimed by atomic cursor; order irrelevant since the
// query keeps min-4 original indices).
// ---------------------------------------------------------------------------
__global__ void build_kernel(const float* __restrict__ h_state,
                             const int* __restrict__ h_faces) {
    int t = blockIdx.x * blockDim.x + threadIdx.x;

    if (t < BS * NV) {
        int b = t / NV, v = t - b * NV;
        const float* xs = h_state + b * 6 * NV;
        float x = xs[v], y = xs[NV + v], z = xs[2 * NV + v];
        int ix = min(max((int)(x * 10.0f), 0), GRIDC - 1);
        int iy = min(max((int)(y * 10.0f), 0), GRIDC - 1);
        int c = b * NCELL + iy * GRIDC + ix;
        int slot = atomicAdd(&g_cellcnt[c], 1);
        if (slot < CAP) g_bins[c * CAP + slot] = make_float4(x, y, z, __int_as_float(v));
    }

    if (t < BS * NF) {
        int b = t / NF, f = t - b * NF;
        const int* F = h_faces + b * 3 * NF;
        int i0 = F[f], i1 = F[NF + f], i2 = F[2 * NF + f];

        const float* xs = h_state + b * 6 * NV;
        const float* ys = xs + NV;
        const float* zs = xs + 2 * NV;

        float x0 = xs[i0], y0 = ys[i0], z0 = zs[i0];
        float e1x = xs[i1] - x0, e1y = ys[i1] - y0, e1z = zs[i1] - z0;
        float e2x = xs[i2] - x0, e2y = ys[i2] - y0, e2z = zs[i2] - z0;

        float nx = e1y * e2z - e1z * e2y;
        float ny = e1z * e2x - e1x * e2z;
        float nz = e1x * e2y - e1y * e2x;
        float nrm = sqrtf(nx * nx + ny * ny + nz * nz) + EPSF;
        nx /= nrm; ny /= nrm; nz /= nrm;

        int base = b * NV;
        int vi0 = base + i0, vi1 = base + i1, vi2 = base + i2;
        atomicAdd(&g_vnsum[vi0 * 3 + 0], nx);
        atomicAdd(&g_vnsum[vi0 * 3 + 1], ny);
        atomicAdd(&g_vnsum[vi0 * 3 + 2], nz);
        atomicAdd(&g_vncnt[vi0], 1.0f);
        atomicAdd(&g_vnsum[vi1 * 3 + 0], nx);
        atomicAdd(&g_vnsum[vi1 * 3 + 1], ny);
        atomicAdd(&g_vnsum[vi1 * 3 + 2], nz);
        atomicAdd(&g_vncnt[vi1], 1.0f);
        atomicAdd(&g_vnsum[vi2 * 3 + 0], nx);
        atomicAdd(&g_vnsum[vi2 * 3 + 1], ny);
        atomicAdd(&g_vnsum[vi2 * 3 + 2], nz);
        atomicAdd(&g_vncnt[vi2], 1.0f);
    }
}

// ---------------------------------------------------------------------------
// K2: warp-per-query ball query over 3x3 cells + loss + per-block reduction.
// Each lane keeps a sorted 4-min list of hit indices; warp merge = 4 rounds
// of warp-min with owner-lane removal (vertices are unique per lane).
// ---------------------------------------------------------------------------
__global__ void __launch_bounds__(256)
query_kernel(const float* __restrict__ pred,
             const float* __restrict__ h_state) {
    __shared__ float s_sum[8];
    __shared__ float s_cnt[8];

    int gwid = (blockIdx.x * blockDim.x + threadIdx.x) >> 5;
    int lane = threadIdx.x & 31;
    int wib  = threadIdx.x >> 5;

    int b = gwid / NQ;

    const float* P = pred + (size_t)gwid * 3;
    float px = P[0], py = P[1], pz = P[2];

    int ix = min(max((int)(px * 10.0f), 0), GRIDC - 1);
    int iy = min(max((int)(py * 10.0f), 0), GRIDC - 1);
    int x0 = max(ix - 1, 0), x1 = min(ix + 1, GRIDC - 1);
    int y0 = max(iy - 1, 0), y1 = min(iy + 1, GRIDC - 1);

    int b0 = IMAXI, b1 = IMAXI, b2 = IMAXI, b3 = IMAXI;

    for (int cy = y0; cy <= y1; cy++) {
        for (int cx = x0; cx <= x1; cx++) {
            int c = b * NCELL + cy * GRIDC + cx;
            int cnt = min(__ldg(&g_cellcnt[c]), CAP);
            const float4* bin = g_bins + (size_t)c * CAP;
            for (int s = lane; s < cnt; s += 32) {
                float4 v = __ldg(bin + s);
                float dx = px - v.x, dy = py - v.y, dz = pz - v.z;
                float d2 = dx * dx + dy * dy + dz * dz;
                if (d2 < R2F) {
                    int id = __float_as_int(v.w);
                    if (id < b3) {
                        b3 = id;
                        if (b3 < b2) { int t = b2; b2 = b3; b3 = t; }
                        if (b2 < b1) { int t = b1; b1 = b2; b2 = t; }
                        if (b1 < b0) { int t = b0; b0 = b1; b1 = t; }
                    }
                }
            }
        }
    }

    // Warp merge: 4 successive global minima
    int res[4];
    #pragma unroll
    for (int k = 0; k < 4; k++) {
        int m = b0;
        #pragma unroll
        for (int o = 16; o; o >>= 1) m = min(m, __shfl_xor_sync(0xffffffffu, m, o));
        res[k] = m;
        if (m != IMAXI && b0 == m) { b0 = b1; b1 = b2; b2 = b3; b3 = IMAXI; }
    }

    if (lane == 0) {
        int cnt = 0;
        while (cnt < 4 && res[cnt] != IMAXI) cnt++;
        int first = (cnt > 0) ? res[0] : 0;   // argmax(within)=0 when no hits
        int idx[4];
        #pragma unroll
        for (int j = 0; j < 4; j++) idx[j] = (j < cnt) ? res[j] : first;

        const float* xs = h_state + b * 6 * NV;
        const float* ys = xs + NV;
        const float* zs = xs + 2 * NV;

        float s = 0.0f, nm = 0.0f;
        #pragma unroll
        for (int j = 0; j < 4; j++) {
            int i = idx[j];
            float vx = xs[i], vy = ys[i], vz = zs[i];
            float denom = g_vncnt[b * NV + i] + EPSF;
            float gx = g_vnsum[(b * NV + i) * 3 + 0] / denom;
            float gy = g_vnsum[(b * NV + i) * 3 + 1] / denom;
            float gz = g_vnsum[(b * NV + i) * 3 + 2] / denom;
            float nr = sqrtf(gx * gx + gy * gy + gz * gz) + EPSF;
            gx /= nr; gy /= nr; gz /= nr;
            float dot = (px - vx) * gx + (py - vy) * gy + (pz - vz) * gz;
            float valid = (dot >= NEG_R) ? (dot - THRESHF) : 0.0f;
            if (valid < 0.0f) { s += valid; nm += 1.0f; }
        }
        float pp = s / (nm + EPSF);
        float pp2 = pp * pp;
        s_sum[wib] = pp2;
        s_cnt[wib] = (pp2 > 0.0f) ? 1.0f : 0.0f;
    }
    __syncthreads();
    if (threadIdx.x == 0) {
        float bs_ = 0.0f, bc_ = 0.0f;
        #pragma unroll
        for (int i = 0; i < 8; i++) { bs_ += s_sum[i]; bc_ += s_cnt[i]; }
        g_psum[blockIdx.x] = bs_;
        g_pcnt[blockIdx.x] = bc_;
    }
}

// ---------------------------------------------------------------------------
// K3: deterministic reduction of 2048 block partials -> scalar loss
// ---------------------------------------------------------------------------
__global__ void finalize_kernel(float* __restrict__ out) {
    __shared__ float ss[512];
    __shared__ float sc[512];
    int t = threadIdx.x;
    float s = 0.0f, c = 0.0f;
    for (int i = t; i < QBLOCKS; i += 512) { s += g_psum[i]; c += g_pcnt[i]; }
    ss[t] = s; sc[t] = c;
    __syncthreads();
    for (int o = 256; o > 0; o >>= 1) {
        if (t < o) { ss[t] += ss[t + o]; sc[t] += sc[t + o]; }
        __syncthreads();
    }
    if (t == 0) out[0] = ss[0] / (sc[0] + EPSF);   // LOSS_WEIGHT = 1
}

// ---------------------------------------------------------------------------
extern "C" void kernel_launch(void* const* d_in, const int* in_sizes, int n_in,
                              void* d_out, int out_size) {
    const float* pred    = (const float*)d_in[0];   // (2, 8192, 3)
    const float* h_state = (const float*)d_in[2];   // (2, 6, 6890)
    const int*   h_faces = (const int*)d_in[3];     // (2, 3, 13776)
    float* out = (float*)d_out;

    int zn = BS * NV * 3;
    zero_kernel<<<(zn + 255) / 256, 256>>>();

    int bn = BS * NF;   // covers BS*NV too (NF > NV)
    build_kernel<<<(bn + 255) / 256, 256>>>(h_state, h_faces);

    query_kernel<<<QBLOCKS, 256>>>(pred, h_state);

    finalize_kernel<<<1, 512>>>(out);
}

// round 3
// speedup vs baseline: 2.2387x; 1.1771x over previous
#include <cuda_runtime.h>
#include <cuda_bf16.h>

#define BS 2
#define NQ 8192
#define NV 6890
#define NF 13776
#define EPSF 1e-7f
#define R2F 0.01f        // f32(0.1*0.1) — matches JAX constant folding
#define NEG_R (-0.1f)
#define THRESHF 0.001f

#define GRIDC 10
#define NCELL (GRIDC * GRIDC)
#define CAP 256
#define IMAXI 0x7fffffff
#define QBLOCKS (BS * NQ / 8)    // 2048 blocks, 8 warps each

// Device globals are zero-initialized at module load; finalize_kernel
// re-zeros them at the end of every replay so the graph is self-consistent.
__device__ float4 g_vn[BS * NV];            // (nx,ny,nz,count) accumulators
__device__ int    g_cellcnt[BS * NCELL];
__device__ float4 g_bins[BS * NCELL * CAP]; // (x,y,z,idx-as-float)
__device__ float  g_loss[2];                // sum, count

// ---------------------------------------------------------------------------
// K1: fused vertex binning + face-normal scatter (vector red: 3 atomics/face)
// ---------------------------------------------------------------------------
__global__ void build_kernel(const float* __restrict__ h_state,
                             const int* __restrict__ h_faces) {
    int t = blockIdx.x * blockDim.x + threadIdx.x;

    if (t < BS * NV) {
        int b = t / NV, v = t - b * NV;
        const float* xs = h_state + b * 6 * NV;
        float x = xs[v], y = xs[NV + v], z = xs[2 * NV + v];
        int ix = min(max((int)(x * 10.0f), 0), GRIDC - 1);
        int iy = min(max((int)(y * 10.0f), 0), GRIDC - 1);
        int c = b * NCELL + iy * GRIDC + ix;
        int slot = atomicAdd(&g_cellcnt[c], 1);
        if (slot < CAP) g_bins[c * CAP + slot] = make_float4(x, y, z, __int_as_float(v));
    }

    if (t < BS * NF) {
        int b = t / NF, f = t - b * NF;
        const int* F = h_faces + b * 3 * NF;
        int i0 = F[f], i1 = F[NF + f], i2 = F[2 * NF + f];

        const float* xs = h_state + b * 6 * NV;
        const float* ys = xs + NV;
        const float* zs = xs + 2 * NV;

        float x0 = xs[i0], y0 = ys[i0], z0 = zs[i0];
        float e1x = xs[i1] - x0, e1y = ys[i1] - y0, e1z = zs[i1] - z0;
        float e2x = xs[i2] - x0, e2y = ys[i2] - y0, e2z = zs[i2] - z0;

        float nx = e1y * e2z - e1z * e2y;
        float ny = e1z * e2x - e1x * e2z;
        float nz = e1x * e2y - e1y * e2x;
        float nrm = sqrtf(nx * nx + ny * ny + nz * nz) + EPSF;
        nx /= nrm; ny /= nrm; nz /= nrm;

        int base = b * NV;
        float one = 1.0f;
        asm volatile("red.global.add.v4.f32 [%0], {%1, %2, %3, %4};"
                     :: "l"(&g_vn[base + i0]), "f"(nx), "f"(ny), "f"(nz), "f"(one) : "memory");
        asm volatile("red.global.add.v4.f32 [%0], {%1, %2, %3, %4};"
                     :: "l"(&g_vn[base + i1]), "f"(nx), "f"(ny), "f"(nz), "f"(one) : "memory");
        asm volatile("red.global.add.v4.f32 [%0], {%1, %2, %3, %4};"
                     :: "l"(&g_vn[base + i2]), "f"(nx), "f"(ny), "f"(nz), "f"(one) : "memory");
    }
}

// ---------------------------------------------------------------------------
// K2: warp-per-query ball query (min-4 indices over 3x3 cells) + parallel
// loss tail (lanes 0-3) + block partial -> single global accumulator.
// ---------------------------------------------------------------------------
__global__ void __launch_bounds__(256)
query_kernel(const float* __restrict__ pred,
             const float* __restrict__ h_state) {
    __shared__ float s_sum[8];
    __shared__ float s_cnt[8];

    int gwid = (blockIdx.x * blockDim.x + threadIdx.x) >> 5;
    int lane = threadIdx.x & 31;
    int wib  = threadIdx.x >> 5;

    int b = gwid / NQ;

    const float* P = pred + (size_t)gwid * 3;
    float px = P[0], py = P[1], pz = P[2];

    int ix = min(max((int)(px * 10.0f), 0), GRIDC - 1);
    int iy = min(max((int)(py * 10.0f), 0), GRIDC - 1);
    int cx0 = max(ix - 1, 0), cx1 = min(ix + 1, GRIDC - 1);
    int cy0 = max(iy - 1, 0), cy1 = min(iy + 1, GRIDC - 1);

    int b0 = IMAXI, b1 = IMAXI, b2 = IMAXI, b3 = IMAXI;

    for (int cy = cy0; cy <= cy1; cy++) {
        for (int cx = cx0; cx <= cx1; cx++) {
            int c = b * NCELL + cy * GRIDC + cx;
            int cnt = min(__ldg(&g_cellcnt[c]), CAP);
            const float4* bin = g_bins + (size_t)c * CAP;
            for (int sb = 0; sb < cnt; sb += 64) {
                int s1 = sb + lane, s2 = s1 + 32;
                bool p1 = s1 < cnt, p2 = s2 < cnt;
                float4 v1, v2;
                if (p1) v1 = __ldg(bin + s1);
                if (p2) v2 = __ldg(bin + s2);
                if (p1) {
                    float dx = px - v1.x, dy = py - v1.y, dz = pz - v1.z;
                    if (dx * dx + dy * dy + dz * dz < R2F) {
                        int id = __float_as_int(v1.w);
                        if (id < b3) {
                            b3 = id;
                            if (b3 < b2) { int t = b2; b2 = b3; b3 = t; }
                            if (b2 < b1) { int t = b1; b1 = b2; b2 = t; }
                            if (b1 < b0) { int t = b0; b0 = b1; b1 = t; }
                        }
                    }
                }
                if (p2) {
                    float dx = px - v2.x, dy = py - v2.y, dz = pz - v2.z;
                    if (dx * dx + dy * dy + dz * dz < R2F) {
                        int id = __float_as_int(v2.w);
                        if (id < b3) {
                            b3 = id;
                            if (b3 < b2) { int t = b2; b2 = b3; b3 = t; }
                            if (b2 < b1) { int t = b1; b1 = b2; b2 = t; }
                            if (b1 < b0) { int t = b0; b0 = b1; b1 = t; }
                        }
                    }
                }
            }
        }
    }

    // Warp merge: 4 successive global minima. Lane k keeps res[k] in `mine`.
    int mine = IMAXI, first = 0, cnt = 0;
    #pragma unroll
    for (int k = 0; k < 4; k++) {
        int m = b0;
        #pragma unroll
        for (int o = 16; o; o >>= 1) m = min(m, __shfl_xor_sync(0xffffffffu, m, o));
        if (lane == k) mine = m;
        if (k == 0 && m != IMAXI) first = m;
        if (m != IMAXI) cnt++;
        if (m != IMAXI && b0 == m) { b0 = b1; b1 = b2; b2 = b3; b3 = IMAXI; }
    }

    // Parallel loss tail: lanes 0-3 handle one neighbor each
    float contrib = 0.0f, nmv = 0.0f;
    if (lane < 4) {
        int i = (lane < cnt) ? mine : first;   // idx=0 when no hits (argmax semantics)
        const float* xs = h_state + b * 6 * NV;
        float vx = __ldg(xs + i);
        float vy = __ldg(xs + NV + i);
        float vz = __ldg(xs + 2 * NV + i);
        float4 vn = __ldg(&g_vn[b * NV + i]);
        float denom = vn.w + EPSF;
        float gx = vn.x / denom, gy = vn.y / denom, gz = vn.z / denom;
        float nr = sqrtf(gx * gx + gy * gy + gz * gz) + EPSF;
        gx /= nr; gy /= nr; gz /= nr;
        float dot = (px - vx) * gx + (py - vy) * gy + (pz - vz) * gz;
        float valid = (dot >= NEG_R) ? (dot - THRESHF) : 0.0f;
        if (valid < 0.0f) { contrib = valid; nmv = 1.0f; }
    }
    contrib += __shfl_xor_sync(0xffffffffu, contrib, 1);
    contrib += __shfl_xor_sync(0xffffffffu, contrib, 2);
    nmv     += __shfl_xor_sync(0xffffffffu, nmv, 1);
    nmv     += __shfl_xor_sync(0xffffffffu, nmv, 2);

    if (lane == 0) {
        float pp = contrib / (nmv + EPSF);
        float pp2 = pp * pp;
        s_sum[wib] = pp2;
        s_cnt[wib] = (pp2 > 0.0f) ? 1.0f : 0.0f;
    }
    __syncthreads();
    if (threadIdx.x == 0) {
        float bs_ = 0.0f, bc_ = 0.0f;
        #pragma unroll
        for (int i = 0; i < 8; i++) { bs_ += s_sum[i]; bc_ += s_cnt[i]; }
        atomicAdd(&g_loss[0], bs_);
        atomicAdd(&g_loss[1], bc_);
    }
}

// ---------------------------------------------------------------------------
// K3: write scalar loss, then re-zero all scratch for the next graph replay
// ---------------------------------------------------------------------------
__global__ void finalize_kernel(float* __restrict__ out) {
    int t = threadIdx.x;
    if (t == 0) {
        out[0] = g_loss[0] / (g_loss[1] + EPSF);   // LOSS_WEIGHT = 1
        g_loss[0] = 0.0f;
        g_loss[1] = 0.0f;
    }
    float4 z4 = make_float4(0.0f, 0.0f, 0.0f, 0.0f);
    for (int i = t; i < BS * NV; i += 1024) g_vn[i] = z4;
    if (t < BS * NCELL) g_cellcnt[t] = 0;
}

// ---------------------------------------------------------------------------
extern "C" void kernel_launch(void* const* d_in, const int* in_sizes, int n_in,
                              void* d_out, int out_size) {
    const float* pred    = (const float*)d_in[0];   // (2, 8192, 3)
    const float* h_state = (const float*)d_in[2];   // (2, 6, 6890)
    const int*   h_faces = (const int*)d_in[3];     // (2, 3, 13776)
    float* out = (float*)d_out;

    int bn = BS * NF;   // covers BS*NV too (NF > NV)
    build_kernel<<<(bn + 255) / 256, 256>>>(h_state, h_faces);

    query_kernel<<<QBLOCKS, 256>>>(pred, h_state);

    finalize_kernel<<<1, 1024>>>(out);
}

// round 4
// speedup vs baseline: 2.5504x; 1.1393x over previous
#include <cuda_runtime.h>
#include <cuda_bf16.h>

#define BS 2
#define NQ 8192
#define NV 6890
#define NF 13776
#define EPSF 1e-7f
#define R2F 0.01f        // f32(0.1*0.1) — matches JAX constant folding
#define NEG_R (-0.1f)
#define THRESHF 0.001f

#define GRIDC 10
#define NSUB (GRIDC * GRIDC * GRIDC)   // 1000 subcells per batch
#define CAP3 40                        // per-subcell capacity; mean 6.9, P(>40)~1e-20
#define IMAXI 0x7fffffff
#define QBLOCKS (BS * NQ / 8)          // 2048 blocks, 8 warps each

// Device globals zero-initialized at module load; finalize_kernel re-zeros
// them at the end of every replay so the captured graph is self-consistent.
__device__ float4 g_vn[BS * NV];              // (nx,ny,nz,count)
__device__ int    g_cnt3[BS * NSUB];
__device__ float4 g_bins3[BS * NSUB * CAP3];  // (x,y,z,idx-as-float)
__device__ float  g_loss[2];                  // sum, count

// ---------------------------------------------------------------------------
// K1: fused 3D vertex binning + face-normal scatter (red.v4: 3 atomics/face)
// ---------------------------------------------------------------------------
__global__ void build_kernel(const float* __restrict__ h_state,
                             const int* __restrict__ h_faces) {
    int t = blockIdx.x * blockDim.x + threadIdx.x;

    if (t < BS * NV) {
        int b = t / NV, v = t - b * NV;
        const float* xs = h_state + b * 6 * NV;
        float x = __ldg(xs + v), y = __ldg(xs + NV + v), z = __ldg(xs + 2 * NV + v);
        int ix = min(max((int)(x * 10.0f), 0), GRIDC - 1);
        int iy = min(max((int)(y * 10.0f), 0), GRIDC - 1);
        int iz = min(max((int)(z * 10.0f), 0), GRIDC - 1);
        int sc = ((b * GRIDC + iy) * GRIDC + ix) * GRIDC + iz;
        int slot = atomicAdd(&g_cnt3[sc], 1);
        if (slot < CAP3)
            g_bins3[(size_t)sc * CAP3 + slot] = make_float4(x, y, z, __int_as_float(v));
    }

    if (t < BS * NF) {
        int b = t / NF, f = t - b * NF;
        const int* F = h_faces + b * 3 * NF;
        int i0 = __ldg(F + f), i1 = __ldg(F + NF + f), i2 = __ldg(F + 2 * NF + f);

        const float* xs = h_state + b * 6 * NV;
        const float* ys = xs + NV;
        const float* zs = xs + 2 * NV;

        float x0 = __ldg(xs + i0), y0 = __ldg(ys + i0), z0 = __ldg(zs + i0);
        float e1x = __ldg(xs + i1) - x0, e1y = __ldg(ys + i1) - y0, e1z = __ldg(zs + i1) - z0;
        float e2x = __ldg(xs + i2) - x0, e2y = __ldg(ys + i2) - y0, e2z = __ldg(zs + i2) - z0;

        float nx = e1y * e2z - e1z * e2y;
        float ny = e1z * e2x - e1x * e2z;
        float nz = e1x * e2y - e1y * e2x;
        float nrm = sqrtf(nx * nx + ny * ny + nz * nz) + EPSF;
        nx /= nrm; ny /= nrm; nz /= nrm;

        int base = b * NV;
        float one = 1.0f;
        asm volatile("red.global.add.v4.f32 [%0], {%1, %2, %3, %4};"
                     :: "l"(&g_vn[base + i0]), "f"(nx), "f"(ny), "f"(nz), "f"(one) : "memory");
        asm volatile("red.global.add.v4.f32 [%0], {%1, %2, %3, %4};"
                     :: "l"(&g_vn[base + i1]), "f"(nx), "f"(ny), "f"(nz), "f"(one) : "memory");
        asm volatile("red.global.add.v4.f32 [%0], {%1, %2, %3, %4};"
                     :: "l"(&g_vn[base + i2]), "f"(nx), "f"(ny), "f"(nz), "f"(one) : "memory");
    }
}

// ---------------------------------------------------------------------------
// K2: warp-per-query ball query over 3x3 columns x up-to-3 z-subcells,
// keeping the 4 smallest vertex indices; parallel loss tail (lanes 0-3).
// ---------------------------------------------------------------------------
__global__ void __launch_bounds__(256)
query_kernel(const float* __restrict__ pred,
             const float* __restrict__ h_state) {
    __shared__ float s_sum[8];
    __shared__ float s_cnt[8];

    int gwid = (blockIdx.x * blockDim.x + threadIdx.x) >> 5;
    int lane = threadIdx.x & 31;
    int wib  = threadIdx.x >> 5;

    int b = gwid / NQ;

    const float* P = pred + (size_t)gwid * 3;
    float px = __ldg(P), py = __ldg(P + 1), pz = __ldg(P + 2);

    int ix = min(max((int)(px * 10.0f), 0), GRIDC - 1);
    int iy = min(max((int)(py * 10.0f), 0), GRIDC - 1);
    int iz = min(max((int)(pz * 10.0f), 0), GRIDC - 1);
    int cx0 = max(ix - 1, 0), cx1 = min(ix + 1, GRIDC - 1);
    int cy0 = max(iy - 1, 0), cy1 = min(iy + 1, GRIDC - 1);
    int cz0 = max(iz - 1, 0), cz1 = min(iz + 1, GRIDC - 1);
    int nzm1 = cz1 - cz0;   // 1 or 2 extra z-subcells

    int b0 = IMAXI, b1 = IMAXI, b2 = IMAXI, b3 = IMAXI;

    for (int cy = cy0; cy <= cy1; cy++) {
        for (int cx = cx0; cx <= cx1; cx++) {
            int sc = ((b * GRIDC + cy) * GRIDC + cx) * GRIDC + cz0;
            int n0 = min(__ldg(&g_cnt3[sc]), CAP3);
            int n1 = (nzm1 >= 1) ? min(__ldg(&g_cnt3[sc + 1]), CAP3) : 0;
            int n2 = (nzm1 >= 2) ? min(__ldg(&g_cnt3[sc + 2]), CAP3) : 0;
            int n01 = n0 + n1;
            int tot = n01 + n2;
            const float4* B0 = g_bins3 + (size_t)sc * CAP3;
            for (int s = lane; s < tot; s += 32) {
                const float4* B; int off;
                if (s < n0)        { B = B0;            off = s; }
                else if (s < n01)  { B = B0 + CAP3;     off = s - n0; }
                else               { B = B0 + 2 * CAP3; off = s - n01; }
                float4 v = __ldg(B + off);
                float dx = px - v.x, dy = py - v.y, dz = pz - v.z;
                if (dx * dx + dy * dy + dz * dz < R2F) {
                    int id = __float_as_int(v.w);
                    if (id < b3) {
                        b3 = id;
                        if (b3 < b2) { int t = b2; b2 = b3; b3 = t; }
                        if (b2 < b1) { int t = b1; b1 = b2; b2 = t; }
                        if (b1 < b0) { int t = b0; b0 = b1; b1 = t; }
                    }
                }
            }
        }
    }

    // Warp merge: 4 successive global minima; lane k keeps k-th result.
    int mine = IMAXI, first = 0, cnt = 0;
    #pragma unroll
    for (int k = 0; k < 4; k++) {
        int m = b0;
        #pragma unroll
        for (int o = 16; o; o >>= 1) m = min(m, __shfl_xor_sync(0xffffffffu, m, o));
        if (lane == k) mine = m;
        if (k == 0 && m != IMAXI) first = m;
        if (m != IMAXI) cnt++;
        if (m != IMAXI && b0 == m) { b0 = b1; b1 = b2; b2 = b3; b3 = IMAXI; }
    }

    // Parallel loss tail: lanes 0-3 handle one neighbor each.
    float contrib = 0.0f, nmv = 0.0f;
    if (lane < 4) {
        int i = (lane < cnt) ? mine : first;   // idx=0 when no hits (argmax semantics)
        const float* xs = h_state + b * 6 * NV;
        float vx = __ldg(xs + i);
        float vy = __ldg(xs + NV + i);
        float vz = __ldg(xs + 2 * NV + i);
        float4 vn = __ldg(&g_vn[b * NV + i]);
        float denom = vn.w + EPSF;
        float gx = vn.x / denom, gy = vn.y / denom, gz = vn.z / denom;
        float nr = sqrtf(gx * gx + gy * gy + gz * gz) + EPSF;
        gx /= nr; gy /= nr; gz /= nr;
        float dot = (px - vx) * gx + (py - vy) * gy + (pz - vz) * gz;
        float valid = (dot >= NEG_R) ? (dot - THRESHF) : 0.0f;
        if (valid < 0.0f) { contrib = valid; nmv = 1.0f; }
    }
    contrib += __shfl_xor_sync(0xffffffffu, contrib, 1);
    contrib += __shfl_xor_sync(0xffffffffu, contrib, 2);
    nmv     += __shfl_xor_sync(0xffffffffu, nmv, 1);
    nmv     += __shfl_xor_sync(0xffffffffu, nmv, 2);

    if (lane == 0) {
        float pp = contrib / (nmv + EPSF);
        float pp2 = pp * pp;
        s_sum[wib] = pp2;
        s_cnt[wib] = (pp2 > 0.0f) ? 1.0f : 0.0f;
    }
    __syncthreads();
    if (threadIdx.x == 0) {
        float bs_ = 0.0f, bc_ = 0.0f;
        #pragma unroll
        for (int i = 0; i < 8; i++) { bs_ += s_sum[i]; bc_ += s_cnt[i]; }
        atomicAdd(&g_loss[0], bs_);
        atomicAdd(&g_loss[1], bc_);
    }
}

// ---------------------------------------------------------------------------
// K3: write scalar loss; re-zero all scratch (parallel across 28 blocks)
// ---------------------------------------------------------------------------
__global__ void finalize_kernel(float* __restrict__ out) {
    int t = blockIdx.x * blockDim.x + threadIdx.x;
    if (t == 0) {
        out[0] = g_loss[0] / (g_loss[1] + EPSF);   // LOSS_WEIGHT = 1
        g_loss[0] = 0.0f;
        g_loss[1] = 0.0f;
    }
    int nthr = gridDim.x * blockDim.x;
    float4 z4 = make_float4(0.0f, 0.0f, 0.0f, 0.0f);
    for (int i = t; i < BS * NV; i += nthr) g_vn[i] = z4;
    for (int i = t; i < BS * NSUB; i += nthr) g_cnt3[i] = 0;
}

// ---------------------------------------------------------------------------
extern "C" void kernel_launch(void* const* d_in, const int* in_sizes, int n_in,
                              void* d_out, int out_size) {
    const float* pred    = (const float*)d_in[0];   // (2, 8192, 3)
    const float* h_state = (const float*)d_in[2];   // (2, 6, 6890)
    const int*   h_faces = (const int*)d_in[3];     // (2, 3, 13776)
    float* out = (float*)d_out;

    int bn = BS * NF;   // covers BS*NV too (NF > NV)
    build_kernel<<<(bn + 127) / 128, 128>>>(h_state, h_faces);

    query_kernel<<<QBLOCKS, 256>>>(pred, h_state);

    finalize_kernel<<<28, 256>>>(out);
}

// round 5
// speedup vs baseline: 2.5902x; 1.0156x over previous
#include <cuda_runtime.h>
#include <cuda_bf16.h>

#define BS 2
#define NQ 8192
#define NV 6890
#define NF 13776
#define EPSF 1e-7f
#define R2F 0.01f        // f32(0.1*0.1) — matches JAX constant folding
#define NEG_R (-0.1f)
#define THRESHF 0.001f

#define GRIDC 10
#define NSUB (GRIDC * GRIDC * GRIDC)
#define CAP3 40
#define IMAXI 0x7fffffff
#define QBLOCKS (BS * NQ / 16)   // 2 queries/warp, 8 warps/block -> 1024 blocks

// Zero-initialized at module load; the last query block re-zeros everything
// at the end of each replay so the captured graph is self-consistent.
__device__ float4 g_vn[BS * NV];              // (nx,ny,nz,count)
__device__ int    g_cnt3[BS * NSUB];
__device__ float4 g_bins3[BS * NSUB * CAP3];  // (x,y,z,idx-as-float)
__device__ float  g_loss[2];                  // sum, count
__device__ unsigned int g_done;

// ---------------------------------------------------------------------------
// K1: fused 3D vertex binning + face-normal scatter (red.v4: 3 atomics/face)
// ---------------------------------------------------------------------------
__global__ void build_kernel(const float* __restrict__ h_state,
                             const int* __restrict__ h_faces) {
    int t = blockIdx.x * blockDim.x + threadIdx.x;

    if (t < BS * NV) {
        int b = t / NV, v = t - b * NV;
        const float* xs = h_state + b * 6 * NV;
        float x = __ldg(xs + v), y = __ldg(xs + NV + v), z = __ldg(xs + 2 * NV + v);
        int ix = min(max((int)(x * 10.0f), 0), GRIDC - 1);
        int iy = min(max((int)(y * 10.0f), 0), GRIDC - 1);
        int iz = min(max((int)(z * 10.0f), 0), GRIDC - 1);
        int sc = ((b * GRIDC + iy) * GRIDC + ix) * GRIDC + iz;
        int slot = atomicAdd(&g_cnt3[sc], 1);
        if (slot < CAP3)
            g_bins3[(size_t)sc * CAP3 + slot] = make_float4(x, y, z, __int_as_float(v));
    }

    if (t < BS * NF) {
        int b = t / NF, f = t - b * NF;
        const int* F = h_faces + b * 3 * NF;
        int i0 = __ldg(F + f), i1 = __ldg(F + NF + f), i2 = __ldg(F + 2 * NF + f);

        const float* xs = h_state + b * 6 * NV;
        const float* ys = xs + NV;
        const float* zs = xs + 2 * NV;

        float x0 = __ldg(xs + i0), y0 = __ldg(ys + i0), z0 = __ldg(zs + i0);
        float e1x = __ldg(xs + i1) - x0, e1y = __ldg(ys + i1) - y0, e1z = __ldg(zs + i1) - z0;
        float e2x = __ldg(xs + i2) - x0, e2y = __ldg(ys + i2) - y0, e2z = __ldg(zs + i2) - z0;

        float nx = e1y * e2z - e1z * e2y;
        float ny = e1z * e2x - e1x * e2z;
        float nz = e1x * e2y - e1y * e2x;
        float nrm = sqrtf(nx * nx + ny * ny + nz * nz) + EPSF;
        nx /= nrm; ny /= nrm; nz /= nrm;

        int base = b * NV;
        float one = 1.0f;
        asm volatile("red.global.add.v4.f32 [%0], {%1, %2, %3, %4};"
                     :: "l"(&g_vn[base + i0]), "f"(nx), "f"(ny), "f"(nz), "f"(one) : "memory");
        asm volatile("red.global.add.v4.f32 [%0], {%1, %2, %3, %4};"
                     :: "l"(&g_vn[base + i1]), "f"(nx), "f"(ny), "f"(nz), "f"(one) : "memory");
        asm volatile("red.global.add.v4.f32 [%0], {%1, %2, %3, %4};"
                     :: "l"(&g_vn[base + i2]), "f"(nx), "f"(ny), "f"(nz), "f"(one) : "memory");
    }
}

// ---------------------------------------------------------------------------
// K2: fused query + finalize. 16 lanes per query (2 queries/warp).
// Ball query keeps the 4 smallest vertex indices over 3x3 columns x <=3
// z-subcells; loss tail on hlanes 0-3; last block writes the scalar loss
// and re-zeros all scratch for the next replay.
// ---------------------------------------------------------------------------
__global__ void __launch_bounds__(256)
query_kernel(const float* __restrict__ pred,
             const float* __restrict__ h_state,
             float* __restrict__ out) {
    __shared__ float s_sum[16];
    __shared__ float s_cnt[16];
    __shared__ bool  s_last;

    int gwid  = (blockIdx.x * blockDim.x + threadIdx.x) >> 5;
    int lane  = threadIdx.x & 31;
    int hlane = lane & 15;
    int half  = lane >> 4;
    int wib   = threadIdx.x >> 5;

    int gq = gwid * 2 + half;          // global query id (0..16383)
    int b  = gq >> 13;                 // batch (NQ = 8192)

    const float* P = pred + (size_t)gq * 3;
    float px = __ldg(P), py = __ldg(P + 1), pz = __ldg(P + 2);

    int ix = min(max((int)(px * 10.0f), 0), GRIDC - 1);
    int iy = min(max((int)(py * 10.0f), 0), GRIDC - 1);
    int iz = min(max((int)(pz * 10.0f), 0), GRIDC - 1);
    int cx0 = max(ix - 1, 0), cx1 = min(ix + 1, GRIDC - 1);
    int cy0 = max(iy - 1, 0), cy1 = min(iy + 1, GRIDC - 1);
    int cz0 = max(iz - 1, 0), cz1 = min(iz + 1, GRIDC - 1);
    int nzm1 = cz1 - cz0;

    int b0 = IMAXI, b1 = IMAXI, b2 = IMAXI, b3 = IMAXI;

    for (int cy = cy0; cy <= cy1; cy++) {
        for (int cx = cx0; cx <= cx1; cx++) {
            int sc = ((b * GRIDC + cy) * GRIDC + cx) * GRIDC + cz0;
            int n0 = min(__ldg(&g_cnt3[sc]), CAP3);
            int n1 = (nzm1 >= 1) ? min(__ldg(&g_cnt3[sc + 1]), CAP3) : 0;
            int n2 = (nzm1 >= 2) ? min(__ldg(&g_cnt3[sc + 2]), CAP3) : 0;
            int n01 = n0 + n1;
            int tot = n01 + n2;
            const float4* B0 = g_bins3 + (size_t)sc * CAP3;
            for (int s = hlane; s < tot; s += 16) {
                const float4* B; int off;
                if (s < n0)        { B = B0;            off = s; }
                else if (s < n01)  { B = B0 + CAP3;     off = s - n0; }
                else               { B = B0 + 2 * CAP3; off = s - n01; }
                float4 v = __ldg(B + off);
                float dx = px - v.x, dy = py - v.y, dz = pz - v.z;
                if (dx * dx + dy * dy + dz * dz < R2F) {
                    int id = __float_as_int(v.w);
                    if (id < b3) {
                        b3 = id;
                        if (b3 < b2) { int t = b2; b2 = b3; b3 = t; }
                        if (b2 < b1) { int t = b1; b1 = b2; b2 = t; }
                        if (b1 < b0) { int t = b0; b0 = b1; b1 = t; }
                    }
                }
            }
        }
    }

    // Per-half merge: 4 successive minima; hlane k keeps k-th result.
    int mine = IMAXI, first = 0, cnt = 0;
    #pragma unroll
    for (int k = 0; k < 4; k++) {
        int m = b0;
        #pragma unroll
        for (int o = 8; o; o >>= 1) m = min(m, __shfl_xor_sync(0xffffffffu, m, o));
        if (hlane == k) mine = m;
        if (k == 0 && m != IMAXI) first = m;
        if (m != IMAXI) cnt++;
        if (m != IMAXI && b0 == m) { b0 = b1; b1 = b2; b2 = b3; b3 = IMAXI; }
    }

    // Loss tail: hlanes 0-3 handle one neighbor each.
    float contrib = 0.0f, nmv = 0.0f;
    if (hlane < 4) {
        int i = (hlane < cnt) ? mine : first;   // idx=0 when no hits (argmax)
        const float* xs = h_state + b * 6 * NV;
        float vx = __ldg(xs + i);
        float vy = __ldg(xs + NV + i);
        float vz = __ldg(xs + 2 * NV + i);
        float4 vn = __ldg(&g_vn[b * NV + i]);
        float denom = vn.w + EPSF;
        float gx = vn.x / denom, gy = vn.y / denom, gz = vn.z / denom;
        float nr = sqrtf(gx * gx + gy * gy + gz * gz) + EPSF;
        gx /= nr; gy /= nr; gz /= nr;
        float dot = (px - vx) * gx + (py - vy) * gy + (pz - vz) * gz;
        float valid = (dot >= NEG_R) ? (dot - THRESHF) : 0.0f;
        if (valid < 0.0f) { contrib = valid; nmv = 1.0f; }
    }
    contrib += __shfl_xor_sync(0xffffffffu, contrib, 1);
    contrib += __shfl_xor_sync(0xffffffffu, contrib, 2);
    nmv     += __shfl_xor_sync(0xffffffffu, nmv, 1);
    nmv     += __shfl_xor_sync(0xffffffffu, nmv, 2);

    if (hlane == 0) {
        float pp = contrib / (nmv + EPSF);
        float pp2 = pp * pp;
        s_sum[wib * 2 + half] = pp2;
        s_cnt[wib * 2 + half] = (pp2 > 0.0f) ? 1.0f : 0.0f;
    }
    __syncthreads();

    if (threadIdx.x == 0) {
        float bs_ = 0.0f, bc_ = 0.0f;
        #pragma unroll
        for (int i = 0; i < 16; i++) { bs_ += s_sum[i]; bc_ += s_cnt[i]; }
        atomicAdd(&g_loss[0], bs_);
        atomicAdd(&g_loss[1], bc_);
        __threadfence();
        unsigned int n = atomicAdd(&g_done, 1u);
        s_last = (n == (unsigned int)(gridDim.x - 1));
    }
    __syncthreads();

    // Last block: finalize + re-zero scratch for the next graph replay.
    if (s_last) {
        int t = threadIdx.x;
        if (t == 0) {
            float ls = atomicAdd(&g_loss[0], 0.0f);
            float lc = atomicAdd(&g_loss[1], 0.0f);
            out[0] = ls / (lc + EPSF);     // LOSS_WEIGHT = 1
            g_loss[0] = 0.0f;
            g_loss[1] = 0.0f;
            g_done = 0u;
        }
        float4 z4 = make_float4(0.0f, 0.0f, 0.0f, 0.0f);
        for (int i = t; i < BS * NV; i += 256) g_vn[i] = z4;
        for (int i = t; i < BS * NSUB; i += 256) g_cnt3[i] = 0;
    }
}

// ---------------------------------------------------------------------------
extern "C" void kernel_launch(void* const* d_in, const int* in_sizes, int n_in,
                              void* d_out, int out_size) {
    const float* pred    = (const float*)d_in[0];   // (2, 8192, 3)
    const float* h_state = (const float*)d_in[2];   // (2, 6, 6890)
    const int*   h_faces = (const int*)d_in[3];     // (2, 3, 13776)
    float* out = (float*)d_out;

    int bn = BS * NF;   // covers BS*NV too (NF > NV)
    build_kernel<<<(bn + 127) / 128, 128>>>(h_state, h_faces);

    query_kernel<<<QBLOCKS, 256>>>(pred, h_state, out);
}